// round 3
// baseline (speedup 1.0000x reference)
#include <cuda_runtime.h>
#include <math.h>

#define BB 16
#define HW 4096
#define NPIX 65536   // BB*HW
#define E 256
#define CIN 256
#define RR 365
#define PT 64        // pixels per block (main)
#define RT 32        // reps per block (main)
#define KC 16        // k chunk

#define N1 23920640u // BB*RR*HW

// Scratch (device globals; no runtime allocation allowed)
__device__ float g_emb[NPIX * E];          // normalized embeddings, [pix][E]
__device__ float g_negreps[2 * RR * E];    // normalized neg reps, [m][r][E]
__device__ float g_psum[NPIX];             // per-pixel sum of probs over r

// ---------------------------------------------------------------------------
// Kernel 1: negative representations
//   neg_offset[r,m,:] = |reps[r]| @ neg_w[m*E: (m+1)*E].T + neg_b
//   reps_neg = l2norm((neg_offset + |reps|) * sign(reps))
// One block per (r, m); thread t computes output channel e = t.
// ---------------------------------------------------------------------------
__global__ __launch_bounds__(256)
void negreps_kernel(const float* __restrict__ reps,
                    const float* __restrict__ neg_w,
                    const float* __restrict__ neg_b) {
    __shared__ __align__(16) float rs[E];
    __shared__ __align__(16) float Ws[16][E];
    __shared__ float red[256];
    int r = blockIdx.x, m = blockIdx.y;
    int t = threadIdx.x;

    rs[t] = reps[r * E + t];
    float off = neg_b[m * E + t];
    const float* wrow = neg_w + (size_t)(m * E + t) * E;

    for (int c0 = 0; c0 < E; c0 += 16) {
        __syncthreads();
        float4 v0 = *(const float4*)(wrow + c0);
        float4 v1 = *(const float4*)(wrow + c0 + 4);
        float4 v2 = *(const float4*)(wrow + c0 + 8);
        float4 v3 = *(const float4*)(wrow + c0 + 12);
        Ws[0][t]  = v0.x; Ws[1][t]  = v0.y; Ws[2][t]  = v0.z; Ws[3][t]  = v0.w;
        Ws[4][t]  = v1.x; Ws[5][t]  = v1.y; Ws[6][t]  = v1.z; Ws[7][t]  = v1.w;
        Ws[8][t]  = v2.x; Ws[9][t]  = v2.y; Ws[10][t] = v2.z; Ws[11][t] = v2.w;
        Ws[12][t] = v3.x; Ws[13][t] = v3.y; Ws[14][t] = v3.z; Ws[15][t] = v3.w;
        __syncthreads();
#pragma unroll
        for (int k = 0; k < 16; k++)
            off = fmaf(fabsf(rs[c0 + k]), Ws[k][t], off);
    }

    float xv = rs[t];
    float sg = (xv > 0.f) ? 1.f : ((xv < 0.f) ? -1.f : 0.f);
    float val = (off + fabsf(xv)) * sg;

    red[t] = val * val;
    __syncthreads();
    for (int s = 128; s > 0; s >>= 1) {
        if (t < s) red[t] += red[t + s];
        __syncthreads();
    }
    float invn = 1.f / fmaxf(sqrtf(red[0]), 1e-12f);
    g_negreps[(size_t)(m * RR + r) * E + t] = val * invn;
}

// ---------------------------------------------------------------------------
// Kernel 2: emb = l2norm(conv1x1(x) + b) over channels, written [pix][E].
// Block: 32 pixels x 256 channels, 256 threads, each 4 pix x 8 e accumulators.
// ---------------------------------------------------------------------------
__global__ __launch_bounds__(256)
void emb_kernel(const float* __restrict__ x,
                const float* __restrict__ conv_w,
                const float* __restrict__ conv_b) {
    __shared__ __align__(16) float As[16][32];
    __shared__ __align__(16) float Bs[16][E];
    __shared__ float ssq[32];
    int t = threadIdx.x;
    int pix0 = blockIdx.x * 32;
    int b = pix0 >> 12;
    int hw0 = pix0 & 4095;
    int ep = t & 31, pg = t >> 5;  // e-lane, pixel group (0..7)

    float acc[4][8];
#pragma unroll
    for (int i = 0; i < 4; i++)
#pragma unroll
        for (int j = 0; j < 8; j++) acc[i][j] = 0.f;
    if (t < 32) ssq[t] = 0.f;

    const float* xb = x + (size_t)b * CIN * HW + hw0;

    for (int k0 = 0; k0 < CIN; k0 += 16) {
        __syncthreads();
#pragma unroll
        for (int j = 0; j < 2; j++) {
            int idx = t + j * 256;
            int kk = idx >> 5, p = idx & 31;
            As[kk][p] = xb[(size_t)(k0 + kk) * HW + p];
        }
        {
            const float* wr = conv_w + (size_t)t * CIN + k0;
            float4 v0 = *(const float4*)(wr);
            float4 v1 = *(const float4*)(wr + 4);
            float4 v2 = *(const float4*)(wr + 8);
            float4 v3 = *(const float4*)(wr + 12);
            Bs[0][t]  = v0.x; Bs[1][t]  = v0.y; Bs[2][t]  = v0.z; Bs[3][t]  = v0.w;
            Bs[4][t]  = v1.x; Bs[5][t]  = v1.y; Bs[6][t]  = v1.z; Bs[7][t]  = v1.w;
            Bs[8][t]  = v2.x; Bs[9][t]  = v2.y; Bs[10][t] = v2.z; Bs[11][t] = v2.w;
            Bs[12][t] = v3.x; Bs[13][t] = v3.y; Bs[14][t] = v3.z; Bs[15][t] = v3.w;
        }
        __syncthreads();
#pragma unroll
        for (int k = 0; k < 16; k++) {
            float4 a4 = *(const float4*)&As[k][pg * 4];
            float av0 = a4.x, av1 = a4.y, av2 = a4.z, av3 = a4.w;
#pragma unroll
            for (int j = 0; j < 8; j++) {
                float bb = Bs[k][ep + 32 * j];
                acc[0][j] = fmaf(av0, bb, acc[0][j]);
                acc[1][j] = fmaf(av1, bb, acc[1][j]);
                acc[2][j] = fmaf(av2, bb, acc[2][j]);
                acc[3][j] = fmaf(av3, bb, acc[3][j]);
            }
        }
    }
    // bias + per-pixel sum of squares
    float part[4] = {0.f, 0.f, 0.f, 0.f};
#pragma unroll
    for (int j = 0; j < 8; j++) {
        float bb = conv_b[ep + 32 * j];
#pragma unroll
        for (int i = 0; i < 4; i++) {
            acc[i][j] += bb;
            part[i] = fmaf(acc[i][j], acc[i][j], part[i]);
        }
    }
#pragma unroll
    for (int i = 0; i < 4; i++) atomicAdd(&ssq[pg * 4 + i], part[i]);
    __syncthreads();
#pragma unroll
    for (int i = 0; i < 4; i++) {
        float invn = 1.f / fmaxf(sqrtf(ssq[pg * 4 + i]), 1e-12f);
        float* dst = g_emb + (size_t)(pix0 + pg * 4 + i) * E;
#pragma unroll
        for (int j = 0; j < 8; j++) dst[ep + 32 * j] = acc[i][j] * invn;
    }
}

// ---------------------------------------------------------------------------
// Kernel 3 helpers
// ---------------------------------------------------------------------------
__global__ void zero_psum() {
    int i = blockIdx.x * blockDim.x + threadIdx.x;
    if (i < NPIX) g_psum[i] = 0.f;
}

// ---------------------------------------------------------------------------
// Kernel 4: main fused GEMM + epilogue.
// Block: 64 pixels x 32 r (x3 modes). 256 threads:
//   pp = t&31 -> pixels pp, pp+32 ; rq = t>>5 -> r = rq*4 + j (j=0..3)
// Unit norms => d^2 = max(2 - 2*dot, 0).
// Writes all 5 outputs; cls_score slot gets UNNORMALIZED probs; per-pixel
// sums accumulated into g_psum for the later normalization pass.
// ---------------------------------------------------------------------------
__global__ __launch_bounds__(256)
void main_kernel(const float* __restrict__ reps,
                 float* __restrict__ out) {
    __shared__ __align__(16) float As[KC][PT + 1];
    __shared__ __align__(16) float Bs[3][KC][RT];
    __shared__ float psum_sh[PT];
    int t = threadIdx.x;
    int pix0 = blockIdx.x * PT;
    int r0 = blockIdx.y * RT;
    int pp = t & 31, rq = t >> 5;

    float acc[2][4][3];
#pragma unroll
    for (int i = 0; i < 2; i++)
#pragma unroll
        for (int j = 0; j < 4; j++)
#pragma unroll
            for (int m = 0; m < 3; m++) acc[i][j][m] = 0.f;
    if (t < PT) psum_sh[t] = 0.f;

    for (int k0 = 0; k0 < E; k0 += KC) {
        __syncthreads();
        {   // A tile: 64 pix x 16 k
            int p = t >> 2;
            int kq = (t & 3) << 2;
            float4 v = *(const float4*)&g_emb[(size_t)(pix0 + p) * E + k0 + kq];
            As[kq + 0][p] = v.x; As[kq + 1][p] = v.y;
            As[kq + 2][p] = v.z; As[kq + 3][p] = v.w;
        }
        if (t < 192) {  // B tile: 3 modes x 32 r x 16 k
            int row = t >> 1;
            int half = (t & 1) << 3;
            int m = row >> 5;
            int r = row & 31;
            int gr = r0 + r;
            float4 v0 = make_float4(0.f, 0.f, 0.f, 0.f);
            float4 v1 = make_float4(0.f, 0.f, 0.f, 0.f);
            if (gr < RR) {
                const float* src = (m == 0)
                    ? (reps + (size_t)gr * E)
                    : (g_negreps + (size_t)((m - 1) * RR + gr) * E);
                v0 = *(const float4*)(src + k0 + half);
                v1 = *(const float4*)(src + k0 + half + 4);
            }
            Bs[m][half + 0][r] = v0.x; Bs[m][half + 1][r] = v0.y;
            Bs[m][half + 2][r] = v0.z; Bs[m][half + 3][r] = v0.w;
            Bs[m][half + 4][r] = v1.x; Bs[m][half + 5][r] = v1.y;
            Bs[m][half + 6][r] = v1.z; Bs[m][half + 7][r] = v1.w;
        }
        __syncthreads();
#pragma unroll
        for (int k = 0; k < KC; k++) {
            float a0 = As[k][pp], a1 = As[k][pp + 32];
#pragma unroll
            for (int m = 0; m < 3; m++) {
                float4 bv = *(const float4*)&Bs[m][k][rq << 2];
                acc[0][0][m] = fmaf(a0, bv.x, acc[0][0][m]);
                acc[0][1][m] = fmaf(a0, bv.y, acc[0][1][m]);
                acc[0][2][m] = fmaf(a0, bv.z, acc[0][2][m]);
                acc[0][3][m] = fmaf(a0, bv.w, acc[0][3][m]);
                acc[1][0][m] = fmaf(a1, bv.x, acc[1][0][m]);
                acc[1][1][m] = fmaf(a1, bv.y, acc[1][1][m]);
                acc[1][2][m] = fmaf(a1, bv.z, acc[1][2][m]);
                acc[1][3][m] = fmaf(a1, bv.w, acc[1][3][m]);
            }
        }
    }

    // Epilogue (inv2s2 = 1/(2*0.5^2) = 2, BETA = 0.3)
    float pl0 = 0.f, pl1 = 0.f;
#pragma unroll
    for (int j = 0; j < 4; j++) {
        int r = r0 + (rq << 2) + j;
        if (r < RR) {
#pragma unroll
            for (int i = 0; i < 2; i++) {
                int p = pix0 + pp + (i << 5);
                int b = p >> 12;
                int hw = p & 4095;
                float d2 = fmaxf(2.f - 2.f * acc[i][j][0], 0.f);
                float e1 = fmaxf(2.f - 2.f * acc[i][j][1], 0.f);
                float e2 = fmaxf(2.f - 2.f * acc[i][j][2], 0.f);
                float d   = sqrtf(d2);
                float dn1 = sqrtf(e1);
                float dn2 = sqrtf(e2);
                float mind2 = fminf(e1, e2);
                float dnmin = fminf(dn1, dn2);
                float clsneg = __expf(-2.f * mind2);   // max_m exp(-dn^2*c)
                float pori   = __expf(-2.f * d2);
                float tt = d + 0.3f * (2.f - dnmin);
                float pr = __expf(-2.f * tt * tt);
                unsigned base = ((unsigned)b * RR + r) * HW + hw;
                out[base]            = pr;       // cls_score (unnormalized)
                out[N1 + base]       = clsneg;   // cls_score_neg
                out[2u * N1 + base]  = d;        // distance
                unsigned dnb = ((unsigned)b * RR + r) * 2u * HW + hw;
                out[3u * N1 + dnb]        = dn1; // distance_neg m=0
                out[3u * N1 + dnb + HW]   = dn2; // distance_neg m=1
                out[5u * N1 + base]  = pori;     // probs_ori
                if (i == 0) pl0 += pr; else pl1 += pr;
            }
        }
    }
    atomicAdd(&psum_sh[pp], pl0);
    atomicAdd(&psum_sh[pp + 32], pl1);
    __syncthreads();
    if (t < PT) atomicAdd(&g_psum[pix0 + t], psum_sh[t]);
}

// ---------------------------------------------------------------------------
// Kernel 5/6: reciprocal of per-pixel sums, then scale cls_score.
// ---------------------------------------------------------------------------
__global__ void recip_psum() {
    int i = blockIdx.x * blockDim.x + threadIdx.x;
    if (i < NPIX) g_psum[i] = 1.f / g_psum[i];
}

__global__ void norm_kernel(float* __restrict__ out) {
    unsigned idx = blockIdx.x * blockDim.x + threadIdx.x;
    if (idx < N1) {
        unsigned hw = idx & 4095u;
        unsigned br = idx >> 12;
        unsigned b = br / RR;
        out[idx] *= g_psum[(b << 12) + hw];
    }
}

// ---------------------------------------------------------------------------
extern "C" void kernel_launch(void* const* d_in, const int* in_sizes, int n_in,
                              void* d_out, int out_size) {
    (void)in_sizes; (void)n_in; (void)out_size;
    const float* x      = (const float*)d_in[0];
    const float* conv_w = (const float*)d_in[1];
    const float* conv_b = (const float*)d_in[2];
    const float* reps   = (const float*)d_in[3];
    const float* neg_w  = (const float*)d_in[4];
    const float* neg_b  = (const float*)d_in[5];
    float* out = (float*)d_out;

    negreps_kernel<<<dim3(RR, 2), 256>>>(reps, neg_w, neg_b);
    emb_kernel<<<NPIX / 32, 256>>>(x, conv_w, conv_b);
    zero_psum<<<NPIX / 256, 256>>>();
    main_kernel<<<dim3(NPIX / PT, (RR + RT - 1) / RT), 256>>>(reps, out);
    recip_psum<<<NPIX / 256, 256>>>();
    norm_kernel<<<(N1 + 255u) / 256u, 256>>>(out);
}

// round 8
// speedup vs baseline: 1.8412x; 1.8412x over previous
#include <cuda_runtime.h>
#include <cstdint>
#include <math.h>

#define BB 16
#define HW 4096
#define NPIX 65536
#define E 256
#define RR 365
#define N1 23920640u

// Scratch (device globals; no runtime allocation allowed)
__device__ float g_emb[NPIX * E];          // normalized embeddings, [pix][E]
__device__ float g_negreps[2 * RR * E];    // normalized neg reps, [m][r][E]
__device__ float g_psum[NPIX];             // per-pixel sum of probs over r

// ---------------------------------------------------------------------------
// mma.sync tf32 helpers (sm_80+ ISA, compiles for plain sm_103)
// ---------------------------------------------------------------------------
__device__ __forceinline__ float f2tf32(float f) {
    uint32_t r;
    asm("cvt.rna.tf32.f32 %0, %1;" : "=r"(r) : "f"(f));
    return __uint_as_float(r);
}

__device__ __forceinline__ void mma_tf32(float c[4],
                                         uint32_t a0, uint32_t a1, uint32_t a2, uint32_t a3,
                                         uint32_t b0, uint32_t b1) {
    asm volatile(
        "mma.sync.aligned.m16n8k8.row.col.f32.tf32.tf32.f32 "
        "{%0,%1,%2,%3}, {%4,%5,%6,%7}, {%8,%9}, {%0,%1,%2,%3};"
        : "+f"(c[0]), "+f"(c[1]), "+f"(c[2]), "+f"(c[3])
        : "r"(a0), "r"(a1), "r"(a2), "r"(a3), "r"(b0), "r"(b1));
}

// ---------------------------------------------------------------------------
// Kernel 1: negative representations (tiny, unchanged)
// ---------------------------------------------------------------------------
__global__ __launch_bounds__(256)
void negreps_kernel(const float* __restrict__ reps,
                    const float* __restrict__ neg_w,
                    const float* __restrict__ neg_b) {
    __shared__ __align__(16) float rs[E];
    __shared__ __align__(16) float Ws[16][E];
    __shared__ float red[256];
    int r = blockIdx.x, m = blockIdx.y;
    int t = threadIdx.x;

    rs[t] = reps[r * E + t];
    float off = neg_b[m * E + t];
    const float* wrow = neg_w + (size_t)(m * E + t) * E;

    for (int c0 = 0; c0 < E; c0 += 16) {
        __syncthreads();
        float4 v0 = *(const float4*)(wrow + c0);
        float4 v1 = *(const float4*)(wrow + c0 + 4);
        float4 v2 = *(const float4*)(wrow + c0 + 8);
        float4 v3 = *(const float4*)(wrow + c0 + 12);
        Ws[0][t]  = v0.x; Ws[1][t]  = v0.y; Ws[2][t]  = v0.z; Ws[3][t]  = v0.w;
        Ws[4][t]  = v1.x; Ws[5][t]  = v1.y; Ws[6][t]  = v1.z; Ws[7][t]  = v1.w;
        Ws[8][t]  = v2.x; Ws[9][t]  = v2.y; Ws[10][t] = v2.z; Ws[11][t] = v2.w;
        Ws[12][t] = v3.x; Ws[13][t] = v3.y; Ws[14][t] = v3.z; Ws[15][t] = v3.w;
        __syncthreads();
#pragma unroll
        for (int k = 0; k < 16; k++)
            off = fmaf(fabsf(rs[c0 + k]), Ws[k][t], off);
    }

    float xv = rs[t];
    float sg = (xv > 0.f) ? 1.f : ((xv < 0.f) ? -1.f : 0.f);
    float val = (off + fabsf(xv)) * sg;

    red[t] = val * val;
    __syncthreads();
    for (int s = 128; s > 0; s >>= 1) {
        if (t < s) red[t] += red[t + s];
        __syncthreads();
    }
    float invn = 1.f / fmaxf(sqrtf(red[0]), 1e-12f);
    g_negreps[(size_t)(m * RR + r) * E + t] = val * invn;
}

// ===========================================================================
// Kernel 2: emb via mma.sync tf32. Block = 64 pix x 256 e, K=256 (16-chunks).
// Dynamic smem:
//   bias @0 (1024B), ssq @1024 (256B)
//   tiles @1536: stage = A k-major [16][72]f (4608B) + B [256][20]f (20480B)
//                = 25088B, x2 stages = 50176B
//   Cs reuse @1536: 64 x 260 floats = 66560B
// total = 68096
// ===========================================================================
#define EMB_ASTRIDE 72
#define EMB_STAGEF  (16 * EMB_ASTRIDE + 256 * 20)   // floats per stage
#define EMB_SMEM    68096

__global__ __launch_bounds__(256)
void emb_tc(const float* __restrict__ x,
            const float* __restrict__ conv_w,
            const float* __restrict__ conv_b) {
    extern __shared__ float smem[];
    float* bias_sh = smem;            // 256
    float* ssq     = smem + 256;      // 64
    float* tiles   = smem + 384;      // stages / Cs
    float* Cs      = tiles;           // reuse, stride 260

    int t = threadIdx.x;
    int w = t >> 5, lane = t & 31;
    int wp = w & 1, wc = w >> 1;              // pix half, e quarter
    int pix0 = blockIdx.x * 64;
    int b = pix0 >> 12, hw0 = pix0 & 4095;

    bias_sh[t] = conv_b[t];
    if (t < 64) ssq[t] = 0.f;

    float c[2][8][4];
#pragma unroll
    for (int mt = 0; mt < 2; mt++)
#pragma unroll
        for (int nt = 0; nt < 8; nt++)
#pragma unroll
            for (int q = 0; q < 4; q++) c[mt][nt][q] = 0.f;

    // loader indices
    int ak = t >> 4;                  // 0..15 (k within chunk)
    int ah = (t & 15) * 4;            // 0..60 (pix offset)
    const float* xrowbase = x + ((size_t)b * E + ak) * HW + hw0 + ah;
    const float* wrow = conv_w + (size_t)t * E;

    float4 aR;
    float4 bR[4];

    // prologue: load chunk 0
    aR = *(const float4*)(xrowbase);
#pragma unroll
    for (int j = 0; j < 4; j++) bR[j] = *(const float4*)(wrow + j * 4);
    {
        float* As = tiles;
        float* Bs = tiles + 16 * EMB_ASTRIDE;
        float4 av = make_float4(f2tf32(aR.x), f2tf32(aR.y), f2tf32(aR.z), f2tf32(aR.w));
        *(float4*)(As + ak * EMB_ASTRIDE + ah) = av;
#pragma unroll
        for (int j = 0; j < 4; j++) {
            float4 bv = make_float4(f2tf32(bR[j].x), f2tf32(bR[j].y),
                                    f2tf32(bR[j].z), f2tf32(bR[j].w));
            *(float4*)(Bs + t * 20 + j * 4) = bv;
        }
    }
    __syncthreads();

#pragma unroll 1
    for (int ch = 0; ch < 16; ch++) {
        // prefetch next chunk into regs
        if (ch < 15) {
            aR = *(const float4*)(xrowbase + (size_t)(ch + 1) * 16 * HW);
#pragma unroll
            for (int j = 0; j < 4; j++)
                bR[j] = *(const float4*)(wrow + (ch + 1) * 16 + j * 4);
        }
        const float* As = tiles + (ch & 1) * EMB_STAGEF;
        const float* Bs = As + 16 * EMB_ASTRIDE;
#pragma unroll
        for (int kk = 0; kk < 16; kk += 8) {
            uint32_t a[2][4];
#pragma unroll
            for (int mt = 0; mt < 2; mt++) {
                int row = wp * 32 + mt * 16 + (lane >> 2);
                int kc = kk + (lane & 3);
                a[mt][0] = __float_as_uint(As[kc * EMB_ASTRIDE + row]);
                a[mt][1] = __float_as_uint(As[kc * EMB_ASTRIDE + row + 8]);
                a[mt][2] = __float_as_uint(As[(kc + 4) * EMB_ASTRIDE + row]);
                a[mt][3] = __float_as_uint(As[(kc + 4) * EMB_ASTRIDE + row + 8]);
            }
#pragma unroll
            for (int nt = 0; nt < 8; nt++) {
                int col = wc * 64 + nt * 8 + (lane >> 2);
                uint32_t b0 = __float_as_uint(Bs[col * 20 + kk + (lane & 3)]);
                uint32_t b1 = __float_as_uint(Bs[col * 20 + kk + 4 + (lane & 3)]);
#pragma unroll
                for (int mt = 0; mt < 2; mt++)
                    mma_tf32(c[mt][nt], a[mt][0], a[mt][1], a[mt][2], a[mt][3], b0, b1);
            }
        }
        if (ch < 15) {
            float* Asn = tiles + ((ch + 1) & 1) * EMB_STAGEF;
            float* Bsn = Asn + 16 * EMB_ASTRIDE;
            float4 av = make_float4(f2tf32(aR.x), f2tf32(aR.y), f2tf32(aR.z), f2tf32(aR.w));
            *(float4*)(Asn + ak * EMB_ASTRIDE + ah) = av;
#pragma unroll
            for (int j = 0; j < 4; j++) {
                float4 bv = make_float4(f2tf32(bR[j].x), f2tf32(bR[j].y),
                                        f2tf32(bR[j].z), f2tf32(bR[j].w));
                *(float4*)(Bsn + t * 20 + j * 4) = bv;
            }
        }
        __syncthreads();
    }

    // stage C to smem (stride 260)
#pragma unroll
    for (int mt = 0; mt < 2; mt++)
#pragma unroll
        for (int nt = 0; nt < 8; nt++) {
            int row = wp * 32 + mt * 16 + (lane >> 2);
            int col = wc * 64 + nt * 8 + 2 * (lane & 3);
            *(float2*)(Cs + row * 260 + col) = make_float2(c[mt][nt][0], c[mt][nt][1]);
            *(float2*)(Cs + (row + 8) * 260 + col) = make_float2(c[mt][nt][2], c[mt][nt][3]);
        }
    __syncthreads();

    // bias + ssq + normalize + write
    {
        int p = t >> 2;
        int es = (t & 3) * 64;
        float v[64];
        const float* crow = Cs + p * 260 + es;
        float part = 0.f;
#pragma unroll
        for (int j = 0; j < 16; j++) {
            float4 q = *(const float4*)(crow + j * 4);
            v[j * 4 + 0] = q.x + bias_sh[es + j * 4 + 0];
            v[j * 4 + 1] = q.y + bias_sh[es + j * 4 + 1];
            v[j * 4 + 2] = q.z + bias_sh[es + j * 4 + 2];
            v[j * 4 + 3] = q.w + bias_sh[es + j * 4 + 3];
            part = fmaf(v[j * 4 + 0], v[j * 4 + 0], part);
            part = fmaf(v[j * 4 + 1], v[j * 4 + 1], part);
            part = fmaf(v[j * 4 + 2], v[j * 4 + 2], part);
            part = fmaf(v[j * 4 + 3], v[j * 4 + 3], part);
        }
        atomicAdd(&ssq[p], part);
        __syncthreads();
        float invn = 1.f / fmaxf(sqrtf(ssq[p]), 1e-12f);
        float* dst = g_emb + (size_t)(pix0 + p) * E + es;
#pragma unroll
        for (int j = 0; j < 16; j++) {
            float4 o;
            o.x = v[j * 4 + 0] * invn;
            o.y = v[j * 4 + 1] * invn;
            o.z = v[j * 4 + 2] * invn;
            o.w = v[j * 4 + 3] * invn;
            *(float4*)(dst + j * 4) = o;
        }
    }
}

// ===========================================================================
// Kernel 3: main GEMM + epilogue via mma.sync tf32.
// Block = 128 pix x 96 cols (32 r x 3 modes, col = m*32 + rl), K=256.
// Dynamic smem:
//   psum_sh @0 (512B)
//   tiles @512: stage = A [128][20]f (10240B) + B [96][20]f (7680B) = 17920B x2
//   Cs reuse @512: 128 x 101 floats = 51712B
// total = 52224
// ===========================================================================
#define MAIN_STAGEF (128 * 20 + 96 * 20)
#define MAIN_SMEM   52224

__global__ __launch_bounds__(256)
void main_tc(const float* __restrict__ reps, float* __restrict__ out) {
    extern __shared__ float smem[];
    float* psum_sh = smem;            // 128
    float* tiles   = smem + 128;
    float* Cs      = tiles;           // reuse, stride 101

    int t = threadIdx.x;
    int w = t >> 5, lane = t & 31;
    int wp = w & 3, wc = w >> 2;      // pix quarter, col half
    int pix0 = blockIdx.x * 128;
    int r0 = blockIdx.y * 32;

    if (t < 128) psum_sh[t] = 0.f;

    float c[2][6][4];
#pragma unroll
    for (int mt = 0; mt < 2; mt++)
#pragma unroll
        for (int nt = 0; nt < 6; nt++)
#pragma unroll
            for (int q = 0; q < 4; q++) c[mt][nt][q] = 0.f;

    // loader indices
    int arow = t >> 1, ahalf = (t & 1) * 8;
    const float* asrc = g_emb + (size_t)(pix0 + arow) * E + ahalf;
    int brow = (t < 192) ? (t >> 1) : 0;      // 0..95
    int bhalf = (t & 1) * 8;
    int bm = brow >> 5, brl = brow & 31, br = r0 + brl;
    bool bvalid = (t < 192) && (br < RR);
    const float* bsrc = (bm == 0) ? (reps + (size_t)(br < RR ? br : 0) * E)
                                  : (g_negreps + (size_t)((bm - 1) * RR + (br < RR ? br : 0)) * E);
    bsrc += bhalf;

    float4 aR0, aR1, bR0, bR1;

    // prologue chunk 0
    aR0 = *(const float4*)(asrc);
    aR1 = *(const float4*)(asrc + 4);
    if (bvalid) { bR0 = *(const float4*)(bsrc); bR1 = *(const float4*)(bsrc + 4); }
    else { bR0 = bR1 = make_float4(0.f, 0.f, 0.f, 0.f); }
    {
        float* As = tiles;
        float* Bs = tiles + 128 * 20;
        *(float4*)(As + arow * 20 + ahalf) =
            make_float4(f2tf32(aR0.x), f2tf32(aR0.y), f2tf32(aR0.z), f2tf32(aR0.w));
        *(float4*)(As + arow * 20 + ahalf + 4) =
            make_float4(f2tf32(aR1.x), f2tf32(aR1.y), f2tf32(aR1.z), f2tf32(aR1.w));
        if (t < 192) {
            *(float4*)(Bs + brow * 20 + bhalf) =
                make_float4(f2tf32(bR0.x), f2tf32(bR0.y), f2tf32(bR0.z), f2tf32(bR0.w));
            *(float4*)(Bs + brow * 20 + bhalf + 4) =
                make_float4(f2tf32(bR1.x), f2tf32(bR1.y), f2tf32(bR1.z), f2tf32(bR1.w));
        }
    }
    __syncthreads();

#pragma unroll 1
    for (int ch = 0; ch < 16; ch++) {
        if (ch < 15) {
            int k0 = (ch + 1) * 16;
            aR0 = *(const float4*)(asrc + k0);
            aR1 = *(const float4*)(asrc + k0 + 4);
            if (bvalid) {
                bR0 = *(const float4*)(bsrc + k0);
                bR1 = *(const float4*)(bsrc + k0 + 4);
            } else { bR0 = bR1 = make_float4(0.f, 0.f, 0.f, 0.f); }
        }
        const float* As = tiles + (ch & 1) * MAIN_STAGEF;
        const float* Bs = As + 128 * 20;
#pragma unroll
        for (int kk = 0; kk < 16; kk += 8) {
            uint32_t a[2][4];
#pragma unroll
            for (int mt = 0; mt < 2; mt++) {
                int row = wp * 32 + mt * 16 + (lane >> 2);
                int kc = kk + (lane & 3);
                a[mt][0] = __float_as_uint(As[row * 20 + kc]);
                a[mt][1] = __float_as_uint(As[(row + 8) * 20 + kc]);
                a[mt][2] = __float_as_uint(As[row * 20 + kc + 4]);
                a[mt][3] = __float_as_uint(As[(row + 8) * 20 + kc + 4]);
            }
#pragma unroll
            for (int nt = 0; nt < 6; nt++) {
                int col = wc * 48 + nt * 8 + (lane >> 2);
                uint32_t b0 = __float_as_uint(Bs[col * 20 + kk + (lane & 3)]);
                uint32_t b1 = __float_as_uint(Bs[col * 20 + kk + 4 + (lane & 3)]);
#pragma unroll
                for (int mt = 0; mt < 2; mt++)
                    mma_tf32(c[mt][nt], a[mt][0], a[mt][1], a[mt][2], a[mt][3], b0, b1);
            }
        }
        if (ch < 15) {
            float* Asn = tiles + ((ch + 1) & 1) * MAIN_STAGEF;
            float* Bsn = Asn + 128 * 20;
            *(float4*)(Asn + arow * 20 + ahalf) =
                make_float4(f2tf32(aR0.x), f2tf32(aR0.y), f2tf32(aR0.z), f2tf32(aR0.w));
            *(float4*)(Asn + arow * 20 + ahalf + 4) =
                make_float4(f2tf32(aR1.x), f2tf32(aR1.y), f2tf32(aR1.z), f2tf32(aR1.w));
            if (t < 192) {
                *(float4*)(Bsn + brow * 20 + bhalf) =
                    make_float4(f2tf32(bR0.x), f2tf32(bR0.y), f2tf32(bR0.z), f2tf32(bR0.w));
                *(float4*)(Bsn + brow * 20 + bhalf + 4) =
                    make_float4(f2tf32(bR1.x), f2tf32(bR1.y), f2tf32(bR1.z), f2tf32(bR1.w));
            }
        }
        __syncthreads();
    }

    // stage C to smem (stride 101, scalar stores)
#pragma unroll
    for (int mt = 0; mt < 2; mt++)
#pragma unroll
        for (int nt = 0; nt < 6; nt++) {
            int row = wp * 32 + mt * 16 + (lane >> 2);
            int col = wc * 48 + nt * 8 + 2 * (lane & 3);
            Cs[row * 101 + col]           = c[mt][nt][0];
            Cs[row * 101 + col + 1]       = c[mt][nt][1];
            Cs[(row + 8) * 101 + col]     = c[mt][nt][2];
            Cs[(row + 8) * 101 + col + 1] = c[mt][nt][3];
        }
    __syncthreads();

    // epilogue: pl = t&31 -> pixels pl+32i; rq = t>>5 -> rl = rq*4+jj
    int pl = t & 31, rq = t >> 5;
    float pacc[4] = {0.f, 0.f, 0.f, 0.f};
#pragma unroll
    for (int i = 0; i < 4; i++) {
        int p = pl + 32 * i;
        int gp = pix0 + p;
        int b = gp >> 12, hw = gp & 4095;
#pragma unroll
        for (int jj = 0; jj < 4; jj++) {
            int rl = rq * 4 + jj;
            int r = r0 + rl;
            if (r < RR) {
                float dot0 = Cs[p * 101 + rl];
                float dot1 = Cs[p * 101 + 32 + rl];
                float dot2 = Cs[p * 101 + 64 + rl];
                float d2 = fmaxf(2.f - 2.f * dot0, 0.f);
                float e1 = fmaxf(2.f - 2.f * dot1, 0.f);
                float e2 = fmaxf(2.f - 2.f * dot2, 0.f);
                float d   = sqrtf(d2);
                float dn1 = sqrtf(e1);
                float dn2 = sqrtf(e2);
                float mind2 = fminf(e1, e2);
                float dnmin = fminf(dn1, dn2);
                float clsneg = __expf(-2.f * mind2);
                float pori   = __expf(-2.f * d2);
                float tt = d + 0.3f * (2.f - dnmin);
                float pr = __expf(-2.f * tt * tt);
                unsigned base = ((unsigned)b * RR + r) * HW + hw;
                out[base]            = pr;       // cls_score (unnormalized)
                out[N1 + base]       = clsneg;   // cls_score_neg
                out[2u * N1 + base]  = d;        // distance
                unsigned dnb = ((unsigned)b * RR + r) * 2u * HW + hw;
                out[3u * N1 + dnb]      = dn1;   // distance_neg m=0
                out[3u * N1 + dnb + HW] = dn2;   // distance_neg m=1
                out[5u * N1 + base]  = pori;     // probs_ori
                pacc[i] += pr;
            }
        }
    }
#pragma unroll
    for (int i = 0; i < 4; i++) atomicAdd(&psum_sh[pl + 32 * i], pacc[i]);
    __syncthreads();
    if (t < 128) atomicAdd(&g_psum[pix0 + t], psum_sh[t]);
}

// ---------------------------------------------------------------------------
// Small kernels
// ---------------------------------------------------------------------------
__global__ void zero_psum() {
    int i = blockIdx.x * blockDim.x + threadIdx.x;
    if (i < NPIX) g_psum[i] = 0.f;
}
__global__ void recip_psum() {
    int i = blockIdx.x * blockDim.x + threadIdx.x;
    if (i < NPIX) g_psum[i] = 1.f / g_psum[i];
}
__global__ void norm_kernel(float* __restrict__ out) {
    unsigned idx = blockIdx.x * blockDim.x + threadIdx.x;
    if (idx < N1) {
        unsigned hw = idx & 4095u;
        unsigned br = idx >> 12;
        unsigned b = br / RR;
        out[idx] *= g_psum[(b << 12) + hw];
    }
}

// ---------------------------------------------------------------------------
extern "C" void kernel_launch(void* const* d_in, const int* in_sizes, int n_in,
                              void* d_out, int out_size) {
    (void)in_sizes; (void)n_in; (void)out_size;
    const float* x      = (const float*)d_in[0];
    const float* conv_w = (const float*)d_in[1];
    const float* conv_b = (const float*)d_in[2];
    const float* reps   = (const float*)d_in[3];
    const float* neg_w  = (const float*)d_in[4];
    const float* neg_b  = (const float*)d_in[5];
    float* out = (float*)d_out;

    cudaFuncSetAttribute(emb_tc, cudaFuncAttributeMaxDynamicSharedMemorySize, EMB_SMEM);
    cudaFuncSetAttribute(main_tc, cudaFuncAttributeMaxDynamicSharedMemorySize, MAIN_SMEM);

    negreps_kernel<<<dim3(RR, 2), 256>>>(reps, neg_w, neg_b);
    emb_tc<<<NPIX / 64, 256, EMB_SMEM>>>(x, conv_w, conv_b);
    zero_psum<<<NPIX / 256, 256>>>();
    main_tc<<<dim3(NPIX / 128, 12), 256, MAIN_SMEM>>>(reps, out);
    recip_psum<<<NPIX / 256, 256>>>();
    norm_kernel<<<(N1 + 255u) / 256u, 256>>>(out);
}